// round 7
// baseline (speedup 1.0000x reference)
#include <cuda_runtime.h>
#include <cstdint>
#include <math.h>

#define NB 64
#define LOOKBACK 32
#define NS 256
#define DM 512
#define DK 128
#define DV 128
#define WST 8                  // stocks per warp in main kernel
#define CPB (NS / (4 * WST))   // CTAs per batch in main = 8
#define NPART CPB              // 8 CTA-partials per batch

// ---- scratch (device globals: allocation-free) ----
__device__ float  g_upart[NB * 4 * DM];     // 4 partial u slices per batch
__device__ float4 g_stock[NS];              // {alpha, gate, lag_floor, lag_ceil}
__device__ float  g_pctx[NB * NPART * DM];  // CTA partial contexts (unnormalized)
__device__ float  g_m[NB * NPART];          // CTA running max
__device__ float  g_l[NB * NPART];          // CTA running sum
__device__ unsigned int g_cnt[NB];          // arrival counters (zeroed in prep)

__device__ __forceinline__ float sigmoidf_(float x) {
    return 1.0f / (1.0f + __expf(-x));
}

// ============================================================================
// Kernel 1: prep. grid (4, NB) x 256 threads. CTA (g, b) computes
// q[b, g*32 .. g*32+32) and the partial u from those 32 k's into g_upart.
// ============================================================================
__global__ __launch_bounds__(256) void prep_kernel(
    const float* __restrict__ query,
    const float* __restrict__ Wq,
    const float* __restrict__ Wk,
    const float* __restrict__ lags,
    const float* __restrict__ gates,
    const void*  __restrict__ mlraw)
{
    __shared__ float  qs[DM];
    __shared__ float  qks[32];
    __shared__ float4 sred[2][DM / 4];

    const int tid = threadIdx.x;    // 0..255
    const int g   = blockIdx.x;     // 0..3 k-slice
    const int b   = blockIdx.y;     // batch

    if (g == 0 && tid == 0) g_cnt[b] = 0u;

    // per-stock meta (one CTA)
    if (g == 0 && b == 0) {
        float ml = 16.0f;
        if (mlraw != nullptr) {
            int   iv = ((const int*)mlraw)[0];
            float fv = ((const float*)mlraw)[0];
            ml = (iv > 0 && iv <= 65536) ? (float)iv : fv;
        }
        float lag = sigmoidf_(lags[tid]) * ml;
        int ifl = min(max((int)floorf(lag), 0), LOOKBACK - 1);
        int icl = min(max((int)ceilf(lag),  0), LOOKBACK - 1);
        float alpha = lag - (float)ifl;
        float gate  = sigmoidf_(gates[tid]);
        g_stock[tid] = make_float4(alpha, gate, (float)ifl, (float)icl);
    }

    qs[tid]       = query[(size_t)b * DM + tid];
    qs[tid + 256] = query[(size_t)b * DM + tid + 256];
    __syncthreads();

    // ---- stage A: q[k] for k in this CTA's 32-slice (warp-per-k, 4 rounds) ----
    const int wid  = tid >> 5;     // 0..7
    const int lane = tid & 31;
    #pragma unroll
    for (int r = 0; r < 4; r++) {
        const int kl = r * 8 + wid;
        const int k  = g * 32 + kl;
        float acc = 0.f;
        #pragma unroll
        for (int i = 0; i < 16; i++)
            acc = fmaf(Wq[(size_t)k * DM + i * 32 + lane], qs[i * 32 + lane], acc);
        #pragma unroll
        for (int off = 16; off; off >>= 1)
            acc += __shfl_xor_sync(0xffffffffu, acc, off);
        if (lane == 0) qks[kl] = acc;
    }
    __syncthreads();

    // ---- stage B: partial u over this CTA's 32 k's, K split 2 ways ----
    const int col  = tid & 127;    // float4 column
    const int half = tid >> 7;     // 0..1
    float4 acc = make_float4(0.f, 0.f, 0.f, 0.f);
    const float4* wkb = (const float4*)Wk + (size_t)(g * 32 + half * 16) * (DM / 4) + col;
    #pragma unroll
    for (int kk = 0; kk < 16; kk++) {
        const float  s = qks[half * 16 + kk];
        const float4 w = wkb[(size_t)kk * (DM / 4)];
        acc.x = fmaf(s, w.x, acc.x); acc.y = fmaf(s, w.y, acc.y);
        acc.z = fmaf(s, w.z, acc.z); acc.w = fmaf(s, w.w, acc.w);
    }
    sred[half][col] = acc;
    __syncthreads();

    if (tid < 128) {
        const float inv = 0.08838834764831845f;  // 1/sqrt(128)
        const float4 a = sred[0][tid], c = sred[1][tid];
        float4 r;
        r.x = (a.x + c.x) * inv; r.y = (a.y + c.y) * inv;
        r.z = (a.z + c.z) * inv; r.w = (a.w + c.w) * inv;
        ((float4*)g_upart)[((size_t)b * 4 + g) * (DM / 4) + tid] = r;
    }
}

// ============================================================================
// Kernel 2: main (two-phase deferred reduction) + fused finish.
// grid (CPB, NB) x 128 threads. Warp owns WST=8 stocks; lane owns 4 float4
// slices (d = lane, 32+lane, 64+lane, 96+lane).
// Phase 1: stream all stocks, lane-local partial dots only (no shfl/exp).
// Reduce:  8 interleaved butterfly reductions, per-warp softmax weights.
// Phase 2: re-stream (L2-resident) to accumulate weighted context.
// ============================================================================
__global__ __launch_bounds__(128, 4) void main_kernel(
    const float* __restrict__ embs,
    const float* __restrict__ Wv,
    float*       __restrict__ out)
{
    __shared__ float4 sctx[4 * (DM / 4)];   // 8 KB combine scratch
    __shared__ float  smf[8];               // [0..3]=m, [4..7]=l per warp
    __shared__ unsigned int slast;

    const int tid  = threadIdx.x;
    const int lane = tid & 31;
    const int wid  = tid >> 5;
    const int b    = blockIdx.y;
    const int sp   = blockIdx.x;
    const int s0   = (sp * 4 + wid) * WST;

    const float4* base = (const float4*)embs + (size_t)b * LOOKBACK * NS * (DM / 4);

    // u[b] = sum of 4 partial slices (16 regs)
    const float4* up = (const float4*)g_upart + (size_t)b * 4 * (DM / 4);
    float4 u0, u1, u2, u3;
    {
        float4 t0 = up[lane],       t1 = up[128 + lane];
        float4 t2 = up[256 + lane], t3 = up[384 + lane];
        u0 = make_float4(t0.x+t1.x+t2.x+t3.x, t0.y+t1.y+t2.y+t3.y,
                         t0.z+t1.z+t2.z+t3.z, t0.w+t1.w+t2.w+t3.w);
        t0 = up[32+lane]; t1 = up[160+lane]; t2 = up[288+lane]; t3 = up[416+lane];
        u1 = make_float4(t0.x+t1.x+t2.x+t3.x, t0.y+t1.y+t2.y+t3.y,
                         t0.z+t1.z+t2.z+t3.z, t0.w+t1.w+t2.w+t3.w);
        t0 = up[64+lane]; t1 = up[192+lane]; t2 = up[320+lane]; t3 = up[448+lane];
        u2 = make_float4(t0.x+t1.x+t2.x+t3.x, t0.y+t1.y+t2.y+t3.y,
                         t0.z+t1.z+t2.z+t3.z, t0.w+t1.w+t2.w+t3.w);
        t0 = up[96+lane]; t1 = up[224+lane]; t2 = up[352+lane]; t3 = up[480+lane];
        u3 = make_float4(t0.x+t1.x+t2.x+t3.x, t0.y+t1.y+t2.y+t3.y,
                         t0.z+t1.z+t2.z+t3.z, t0.w+t1.w+t2.w+t3.w);
    }

    // ---- Phase 1: lane-local partial dots, pure streaming ----
    float p[WST];
    #pragma unroll
    for (int i = 0; i < WST; i++) {
        const int s = s0 + i;
        const float4 mt = g_stock[s];
        const float4* rf = base + ((int)mt.z * NS + s) * (DM / 4);
        const float4* rc = base + ((int)mt.w * NS + s) * (DM / 4);
        const float4 f0 = rf[lane], f1 = rf[32+lane], f2 = rf[64+lane], f3 = rf[96+lane];
        const float4 c0 = rc[lane], c1 = rc[32+lane], c2 = rc[64+lane], c3 = rc[96+lane];
        const float a = mt.x, oma = 1.0f - mt.x;

        float4 e0, e1, e2, e3;
        e0.x = oma*f0.x + a*c0.x; e0.y = oma*f0.y + a*c0.y; e0.z = oma*f0.z + a*c0.z; e0.w = oma*f0.w + a*c0.w;
        e1.x = oma*f1.x + a*c1.x; e1.y = oma*f1.y + a*c1.y; e1.z = oma*f1.z + a*c1.z; e1.w = oma*f1.w + a*c1.w;
        e2.x = oma*f2.x + a*c2.x; e2.y = oma*f2.y + a*c2.y; e2.z = oma*f2.z + a*c2.z; e2.w = oma*f2.w + a*c2.w;
        e3.x = oma*f3.x + a*c3.x; e3.y = oma*f3.y + a*c3.y; e3.z = oma*f3.z + a*c3.z; e3.w = oma*f3.w + a*c3.w;

        const float q0 = e0.x*u0.x + e0.y*u0.y + e0.z*u0.z + e0.w*u0.w;
        const float q1 = e1.x*u1.x + e1.y*u1.y + e1.z*u1.z + e1.w*u1.w;
        const float q2 = e2.x*u2.x + e2.y*u2.y + e2.z*u2.z + e2.w*u2.w;
        const float q3 = e3.x*u3.x + e3.y*u3.y + e3.z*u3.z + e3.w*u3.w;
        p[i] = (q0 + q1) + (q2 + q3);
    }

    // ---- interleaved butterfly reductions (8 independent chains) ----
    #pragma unroll
    for (int off = 16; off; off >>= 1) {
        #pragma unroll
        for (int i = 0; i < WST; i++)
            p[i] += __shfl_xor_sync(0xffffffffu, p[i], off);
    }

    // ---- per-warp softmax over its 8 stocks (lane-redundant, no comms) ----
    float m = -INFINITY;
    #pragma unroll
    for (int i = 0; i < WST; i++) {
        p[i] *= g_stock[s0 + i].y;     // gate (1/sqrt(dk) folded into u)
        m = fmaxf(m, p[i]);
    }
    float l = 0.f;
    #pragma unroll
    for (int i = 0; i < WST; i++) {
        p[i] = __expf(p[i] - m);
        l += p[i];
    }

    // ---- Phase 2: re-stream (L2-resident) and accumulate weighted ctx ----
    float4 x0 = make_float4(0.f,0.f,0.f,0.f), x1 = x0, x2 = x0, x3 = x0;
    #pragma unroll
    for (int i = 0; i < WST; i++) {
        const int s = s0 + i;
        const float4 mt = g_stock[s];
        const float4* rf = base + ((int)mt.z * NS + s) * (DM / 4);
        const float4* rc = base + ((int)mt.w * NS + s) * (DM / 4);
        const float4 f0 = rf[lane], f1 = rf[32+lane], f2 = rf[64+lane], f3 = rf[96+lane];
        const float4 c0 = rc[lane], c1 = rc[32+lane], c2 = rc[64+lane], c3 = rc[96+lane];
        const float a = mt.x, oma = 1.0f - mt.x;
        const float w = p[i];

        x0.x += w*(oma*f0.x + a*c0.x); x0.y += w*(oma*f0.y + a*c0.y);
        x0.z += w*(oma*f0.z + a*c0.z); x0.w += w*(oma*f0.w + a*c0.w);
        x1.x += w*(oma*f1.x + a*c1.x); x1.y += w*(oma*f1.y + a*c1.y);
        x1.z += w*(oma*f1.z + a*c1.z); x1.w += w*(oma*f1.w + a*c1.w);
        x2.x += w*(oma*f2.x + a*c2.x); x2.y += w*(oma*f2.y + a*c2.y);
        x2.z += w*(oma*f2.z + a*c2.z); x2.w += w*(oma*f2.w + a*c2.w);
        x3.x += w*(oma*f3.x + a*c3.x); x3.y += w*(oma*f3.y + a*c3.y);
        x3.z += w*(oma*f3.z + a*c3.z); x3.w += w*(oma*f3.w + a*c3.w);
    }

    // ---- CTA combine of 4 warp partials ----
    if (lane == 0) { smf[wid] = m; smf[4 + wid] = l; }
    sctx[wid * 128 + lane]      = x0;
    sctx[wid * 128 + 32 + lane] = x1;
    sctx[wid * 128 + 64 + lane] = x2;
    sctx[wid * 128 + 96 + lane] = x3;
    __syncthreads();

    const float m0 = smf[0], m1 = smf[1], m2 = smf[2], m3 = smf[3];
    const float mg = fmaxf(fmaxf(m0, m1), fmaxf(m2, m3));
    const float w0 = __expf(m0 - mg), w1 = __expf(m1 - mg);
    const float w2 = __expf(m2 - mg), w3 = __expf(m3 - mg);

    const int idx = b * NPART + sp;
    if (tid == 0) {
        g_m[idx] = mg;
        g_l[idx] = w0 * smf[4] + w1 * smf[5] + w2 * smf[6] + w3 * smf[7];
    }
    const float4 a0 = sctx[tid], a1 = sctx[128 + tid], a2 = sctx[256 + tid], a3 = sctx[384 + tid];
    float4 comb;
    comb.x = w0*a0.x + w1*a1.x + w2*a2.x + w3*a3.x;
    comb.y = w0*a0.y + w1*a1.y + w2*a2.y + w3*a3.y;
    comb.z = w0*a0.z + w1*a1.z + w2*a2.z + w3*a3.z;
    comb.w = w0*a0.w + w1*a1.w + w2*a2.w + w3*a3.w;
    ((float4*)g_pctx)[(size_t)idx * (DM / 4) + tid] = comb;

    // ---- fused finish: last CTA of batch b combines + applies W_v ----
    __threadfence();
    __syncthreads();
    if (tid == 0) slast = atomicAdd(&g_cnt[b], 1u);
    __syncthreads();
    if (slast == NPART - 1) {
        float mv[NPART];
        float mgf = -INFINITY;
        #pragma unroll
        for (int i = 0; i < NPART; i++) { mv[i] = g_m[b * NPART + i]; mgf = fmaxf(mgf, mv[i]); }
        float L = 0.f;
        float ws[NPART];
        #pragma unroll
        for (int i = 0; i < NPART; i++) {
            const float w = __expf(mv[i] - mgf);
            ws[i] = w;
            L += w * g_l[b * NPART + i];
        }
        const float invL = 1.0f / L;

        float4 acc = make_float4(0.f, 0.f, 0.f, 0.f);
        const float4* pc = (const float4*)g_pctx + (size_t)b * NPART * (DM / 4) + tid;
        #pragma unroll
        for (int i = 0; i < NPART; i++) {
            const float4 v = pc[(size_t)i * (DM / 4)];
            const float  w = ws[i] * invL;
            acc.x += w * v.x; acc.y += w * v.y; acc.z += w * v.z; acc.w += w * v.w;
        }
        __syncthreads();
        sctx[tid] = acc;             // ctx_emb slice
        __syncthreads();

        // context[b, v] = sum_d ctx_emb[d] * Wv[v, d]   (thread v = tid)
        float s0a = 0.f, s1a = 0.f, s2a = 0.f, s3a = 0.f;
        const float4* wv = (const float4*)Wv + (size_t)tid * (DM / 4);
        #pragma unroll 8
        for (int d = 0; d < DM / 4; d += 4) {
            const float4 wa = wv[d],     ca = sctx[d];
            const float4 wb = wv[d + 1], cb = sctx[d + 1];
            const float4 wc = wv[d + 2], cc = sctx[d + 2];
            const float4 wd = wv[d + 3], cd = sctx[d + 3];
            s0a += wa.x*ca.x + wa.y*ca.y + wa.z*ca.z + wa.w*ca.w;
            s1a += wb.x*cb.x + wb.y*cb.y + wb.z*cb.z + wb.w*cb.w;
            s2a += wc.x*cc.x + wc.y*cc.y + wc.z*cc.z + wc.w*cc.w;
            s3a += wd.x*cd.x + wd.y*cd.y + wd.z*cd.z + wd.w*cd.w;
        }
        out[(size_t)b * DV + tid] = (s0a + s1a) + (s2a + s3a);
    }
}

// ============================================================================
extern "C" void kernel_launch(void* const* d_in, const int* in_sizes, int n_in,
                              void* d_out, int out_size)
{
    const float* query = (const float*)d_in[0];   // [64, 512]
    const float* embs  = (const float*)d_in[1];   // [64, 32, 256, 512]
    const float* Wq    = (const float*)d_in[2];   // [128, 512]
    const float* Wk    = (const float*)d_in[3];   // [128, 512]
    const float* Wv    = (const float*)d_in[4];   // [128, 512]
    const float* lags  = (const float*)d_in[5];   // [256]
    const float* gates = (const float*)d_in[6];   // [256]
    const void*  ml    = (n_in > 7) ? d_in[7] : nullptr;

    prep_kernel<<<dim3(4, NB), 256>>>(query, Wq, Wk, lags, gates, ml);
    main_kernel<<<dim3(CPB, NB), 128>>>(embs, Wv, (float*)d_out);
}

// round 8
// speedup vs baseline: 1.4130x; 1.4130x over previous
#include <cuda_runtime.h>
#include <cstdint>
#include <math.h>

#define NB 64
#define LOOKBACK 32
#define NS 256
#define DM 512
#define DK 128
#define DV 128
#define WST 4                  // stocks per warp in main kernel
#define WPC 8                  // warps per CTA in main
#define CPB (NS / (WPC * WST)) // CTAs per batch in main = 8
#define NPART CPB              // 8 CTA-partials per batch

// ---- scratch (device globals: allocation-free) ----
__device__ float  g_upart[NB * 4 * DM];     // 4 partial u slices per batch
__device__ float4 g_stock[NS];              // {alpha, gate, lag_floor, lag_ceil}
__device__ float  g_pctx[NB * NPART * DM];  // CTA partial contexts (unnormalized)
__device__ float  g_m[NB * NPART];          // CTA running max
__device__ float  g_l[NB * NPART];          // CTA running sum
__device__ unsigned int g_cnt[NB];          // arrival counters (zeroed in prep)

__device__ __forceinline__ float sigmoidf_(float x) {
    return 1.0f / (1.0f + __expf(-x));
}

// ============================================================================
// Kernel 1: prep. grid (4, NB) x 256 threads. CTA (g, b) computes
// q[b, g*32 .. g*32+32) and the partial u from those 32 k's into g_upart.
// ============================================================================
__global__ __launch_bounds__(256) void prep_kernel(
    const float* __restrict__ query,
    const float* __restrict__ Wq,
    const float* __restrict__ Wk,
    const float* __restrict__ lags,
    const float* __restrict__ gates,
    const void*  __restrict__ mlraw)
{
    __shared__ float  qs[DM];
    __shared__ float  qks[32];
    __shared__ float4 sred[2][DM / 4];

    const int tid = threadIdx.x;    // 0..255
    const int g   = blockIdx.x;     // 0..3 k-slice
    const int b   = blockIdx.y;     // batch

    if (g == 0 && tid == 0) g_cnt[b] = 0u;

    // per-stock meta (one CTA)
    if (g == 0 && b == 0) {
        float ml = 16.0f;
        if (mlraw != nullptr) {
            int   iv = ((const int*)mlraw)[0];
            float fv = ((const float*)mlraw)[0];
            ml = (iv > 0 && iv <= 65536) ? (float)iv : fv;
        }
        float lag = sigmoidf_(lags[tid]) * ml;
        int ifl = min(max((int)floorf(lag), 0), LOOKBACK - 1);
        int icl = min(max((int)ceilf(lag),  0), LOOKBACK - 1);
        float alpha = lag - (float)ifl;
        float gate  = sigmoidf_(gates[tid]);
        g_stock[tid] = make_float4(alpha, gate, (float)ifl, (float)icl);
    }

    qs[tid]       = query[(size_t)b * DM + tid];
    qs[tid + 256] = query[(size_t)b * DM + tid + 256];
    __syncthreads();

    // ---- stage A: q[k] for this CTA's 32-slice (warp-per-k, 4 rounds) ----
    const int wid  = tid >> 5;     // 0..7
    const int lane = tid & 31;
    #pragma unroll
    for (int r = 0; r < 4; r++) {
        const int kl = r * 8 + wid;
        const int k  = g * 32 + kl;
        float acc = 0.f;
        #pragma unroll
        for (int i = 0; i < 16; i++)
            acc = fmaf(Wq[(size_t)k * DM + i * 32 + lane], qs[i * 32 + lane], acc);
        #pragma unroll
        for (int off = 16; off; off >>= 1)
            acc += __shfl_xor_sync(0xffffffffu, acc, off);
        if (lane == 0) qks[kl] = acc;
    }
    __syncthreads();

    // ---- stage B: partial u over this CTA's 32 k's, K split 2 ways ----
    const int col  = tid & 127;    // float4 column
    const int half = tid >> 7;     // 0..1
    float4 acc = make_float4(0.f, 0.f, 0.f, 0.f);
    const float4* wkb = (const float4*)Wk + (size_t)(g * 32 + half * 16) * (DM / 4) + col;
    #pragma unroll
    for (int kk = 0; kk < 16; kk++) {
        const float  s = qks[half * 16 + kk];
        const float4 w = wkb[(size_t)kk * (DM / 4)];
        acc.x = fmaf(s, w.x, acc.x); acc.y = fmaf(s, w.y, acc.y);
        acc.z = fmaf(s, w.z, acc.z); acc.w = fmaf(s, w.w, acc.w);
    }
    sred[half][col] = acc;
    __syncthreads();

    if (tid < 128) {
        const float inv = 0.08838834764831845f;  // 1/sqrt(128)
        const float4 a = sred[0][tid], c = sred[1][tid];
        float4 r;
        r.x = (a.x + c.x) * inv; r.y = (a.y + c.y) * inv;
        r.z = (a.z + c.z) * inv; r.w = (a.w + c.w) * inv;
        ((float4*)g_upart)[((size_t)b * 4 + g) * (DM / 4) + tid] = r;
    }
}

// ============================================================================
// Kernel 2: main (two-phase deferred reduction, 8 warps/CTA) + fused finish.
// grid (CPB, NB) x 256 threads. Warp owns WST=4 stocks; lane owns 4 float4
// slices. Phase 1: lane-local dots only. Reduce once. Phase 2: weighted ctx.
// ============================================================================
__global__ __launch_bounds__(256, 2) void main_kernel(
    const float* __restrict__ embs,
    const float* __restrict__ Wv,
    float*       __restrict__ out)
{
    __shared__ float4 sctx[WPC * (DM / 4)];   // 16 KB combine scratch
    __shared__ float  smf[2 * WPC];           // [0..7]=m, [8..15]=l per warp
    __shared__ unsigned int slast;

    const int tid  = threadIdx.x;
    const int lane = tid & 31;
    const int wid  = tid >> 5;        // 0..7
    const int b    = blockIdx.y;
    const int sp   = blockIdx.x;
    const int s0   = (sp * WPC + wid) * WST;

    const float4* base = (const float4*)embs + (size_t)b * LOOKBACK * NS * (DM / 4);

    // u[b] = sum of 4 partial slices (16 regs)
    const float4* up = (const float4*)g_upart + (size_t)b * 4 * (DM / 4);
    float4 u0, u1, u2, u3;
    {
        float4 t0 = up[lane],       t1 = up[128 + lane];
        float4 t2 = up[256 + lane], t3 = up[384 + lane];
        u0 = make_float4(t0.x+t1.x+t2.x+t3.x, t0.y+t1.y+t2.y+t3.y,
                         t0.z+t1.z+t2.z+t3.z, t0.w+t1.w+t2.w+t3.w);
        t0 = up[32+lane]; t1 = up[160+lane]; t2 = up[288+lane]; t3 = up[416+lane];
        u1 = make_float4(t0.x+t1.x+t2.x+t3.x, t0.y+t1.y+t2.y+t3.y,
                         t0.z+t1.z+t2.z+t3.z, t0.w+t1.w+t2.w+t3.w);
        t0 = up[64+lane]; t1 = up[192+lane]; t2 = up[320+lane]; t3 = up[448+lane];
        u2 = make_float4(t0.x+t1.x+t2.x+t3.x, t0.y+t1.y+t2.y+t3.y,
                         t0.z+t1.z+t2.z+t3.z, t0.w+t1.w+t2.w+t3.w);
        t0 = up[96+lane]; t1 = up[224+lane]; t2 = up[352+lane]; t3 = up[480+lane];
        u3 = make_float4(t0.x+t1.x+t2.x+t3.x, t0.y+t1.y+t2.y+t3.y,
                         t0.z+t1.z+t2.z+t3.z, t0.w+t1.w+t2.w+t3.w);
    }

    // ---- Phase 1: lane-local partial dots, pure streaming ----
    float p[WST];
    #pragma unroll
    for (int i = 0; i < WST; i++) {
        const int s = s0 + i;
        const float4 mt = g_stock[s];
        const float4* rf = base + ((int)mt.z * NS + s) * (DM / 4);
        const float4* rc = base + ((int)mt.w * NS + s) * (DM / 4);
        const float4 f0 = rf[lane], f1 = rf[32+lane], f2 = rf[64+lane], f3 = rf[96+lane];
        const float4 c0 = rc[lane], c1 = rc[32+lane], c2 = rc[64+lane], c3 = rc[96+lane];
        const float a = mt.x, oma = 1.0f - mt.x;

        float4 e0, e1, e2, e3;
        e0.x = oma*f0.x + a*c0.x; e0.y = oma*f0.y + a*c0.y; e0.z = oma*f0.z + a*c0.z; e0.w = oma*f0.w + a*c0.w;
        e1.x = oma*f1.x + a*c1.x; e1.y = oma*f1.y + a*c1.y; e1.z = oma*f1.z + a*c1.z; e1.w = oma*f1.w + a*c1.w;
        e2.x = oma*f2.x + a*c2.x; e2.y = oma*f2.y + a*c2.y; e2.z = oma*f2.z + a*c2.z; e2.w = oma*f2.w + a*c2.w;
        e3.x = oma*f3.x + a*c3.x; e3.y = oma*f3.y + a*c3.y; e3.z = oma*f3.z + a*c3.z; e3.w = oma*f3.w + a*c3.w;

        const float q0 = e0.x*u0.x + e0.y*u0.y + e0.z*u0.z + e0.w*u0.w;
        const float q1 = e1.x*u1.x + e1.y*u1.y + e1.z*u1.z + e1.w*u1.w;
        const float q2 = e2.x*u2.x + e2.y*u2.y + e2.z*u2.z + e2.w*u2.w;
        const float q3 = e3.x*u3.x + e3.y*u3.y + e3.z*u3.z + e3.w*u3.w;
        p[i] = (q0 + q1) + (q2 + q3);
    }

    // ---- interleaved butterfly reductions (4 independent chains) ----
    #pragma unroll
    for (int off = 16; off; off >>= 1) {
        #pragma unroll
        for (int i = 0; i < WST; i++)
            p[i] += __shfl_xor_sync(0xffffffffu, p[i], off);
    }

    // ---- per-warp softmax over its 4 stocks (lane-redundant, no comms) ----
    float m = -INFINITY;
    #pragma unroll
    for (int i = 0; i < WST; i++) {
        p[i] *= g_stock[s0 + i].y;     // gate (1/sqrt(dk) folded into u)
        m = fmaxf(m, p[i]);
    }
    float l = 0.f;
    #pragma unroll
    for (int i = 0; i < WST; i++) {
        p[i] = __expf(p[i] - m);
        l += p[i];
    }

    // ---- Phase 2: re-stream (L2-resident) and accumulate weighted ctx ----
    float4 x0 = make_float4(0.f,0.f,0.f,0.f), x1 = x0, x2 = x0, x3 = x0;
    #pragma unroll
    for (int i = 0; i < WST; i++) {
        const int s = s0 + i;
        const float4 mt = g_stock[s];
        const float4* rf = base + ((int)mt.z * NS + s) * (DM / 4);
        const float4* rc = base + ((int)mt.w * NS + s) * (DM / 4);
        const float4 f0 = rf[lane], f1 = rf[32+lane], f2 = rf[64+lane], f3 = rf[96+lane];
        const float4 c0 = rc[lane], c1 = rc[32+lane], c2 = rc[64+lane], c3 = rc[96+lane];
        const float a = mt.x, oma = 1.0f - mt.x;
        const float w = p[i];

        x0.x += w*(oma*f0.x + a*c0.x); x0.y += w*(oma*f0.y + a*c0.y);
        x0.z += w*(oma*f0.z + a*c0.z); x0.w += w*(oma*f0.w + a*c0.w);
        x1.x += w*(oma*f1.x + a*c1.x); x1.y += w*(oma*f1.y + a*c1.y);
        x1.z += w*(oma*f1.z + a*c1.z); x1.w += w*(oma*f1.w + a*c1.w);
        x2.x += w*(oma*f2.x + a*c2.x); x2.y += w*(oma*f2.y + a*c2.y);
        x2.z += w*(oma*f2.z + a*c2.z); x2.w += w*(oma*f2.w + a*c2.w);
        x3.x += w*(oma*f3.x + a*c3.x); x3.y += w*(oma*f3.y + a*c3.y);
        x3.z += w*(oma*f3.z + a*c3.z); x3.w += w*(oma*f3.w + a*c3.w);
    }

    // ---- CTA combine of 8 warp partials ----
    if (lane == 0) { smf[wid] = m; smf[WPC + wid] = l; }
    sctx[wid * 128 + lane]      = x0;
    sctx[wid * 128 + 32 + lane] = x1;
    sctx[wid * 128 + 64 + lane] = x2;
    sctx[wid * 128 + 96 + lane] = x3;
    __syncthreads();

    // threads 0..127: combine 8 partials for one float4 column each
    const int idx = b * NPART + sp;
    if (tid < 128) {
        float mg = -INFINITY;
        #pragma unroll
        for (int i = 0; i < WPC; i++) mg = fmaxf(mg, smf[i]);
        float w[WPC];
        #pragma unroll
        for (int i = 0; i < WPC; i++) w[i] = __expf(smf[i] - mg);
        if (tid == 0) {
            float L = 0.f;
            #pragma unroll
            for (int i = 0; i < WPC; i++) L += w[i] * smf[WPC + i];
            g_m[idx] = mg;
            g_l[idx] = L;
        }
        float4 comb = make_float4(0.f, 0.f, 0.f, 0.f);
        #pragma unroll
        for (int i = 0; i < WPC; i++) {
            const float4 v = sctx[i * 128 + tid];
            comb.x += w[i] * v.x; comb.y += w[i] * v.y;
            comb.z += w[i] * v.z; comb.w += w[i] * v.w;
        }
        ((float4*)g_pctx)[(size_t)idx * (DM / 4) + tid] = comb;
    }

    // ---- fused finish: last CTA of batch b combines + applies W_v ----
    __threadfence();
    __syncthreads();
    if (tid == 0) slast = atomicAdd(&g_cnt[b], 1u);
    __syncthreads();
    if (slast == NPART - 1) {
        if (tid < 128) {
            float mv[NPART];
            float mgf = -INFINITY;
            #pragma unroll
            for (int i = 0; i < NPART; i++) { mv[i] = g_m[b * NPART + i]; mgf = fmaxf(mgf, mv[i]); }
            float L = 0.f;
            float ws[NPART];
            #pragma unroll
            for (int i = 0; i < NPART; i++) {
                const float w = __expf(mv[i] - mgf);
                ws[i] = w;
                L += w * g_l[b * NPART + i];
            }
            const float invL = 1.0f / L;

            float4 acc = make_float4(0.f, 0.f, 0.f, 0.f);
            const float4* pc = (const float4*)g_pctx + (size_t)b * NPART * (DM / 4) + tid;
            #pragma unroll
            for (int i = 0; i < NPART; i++) {
                const float4 v = pc[(size_t)i * (DM / 4)];
                const float  w = ws[i] * invL;
                acc.x += w * v.x; acc.y += w * v.y; acc.z += w * v.z; acc.w += w * v.w;
            }
            sctx[tid] = acc;             // ctx_emb slice (cols 0..127)
        }
        __syncthreads();

        // context[b, v] = sum_d ctx_emb[d] * Wv[v, d]
        // 256 threads: v = tid & 127, half = tid >> 7 sums 64 float4 each
        const int v    = tid & 127;
        const int half = tid >> 7;
        float s0a = 0.f, s1a = 0.f;
        const float4* wv = (const float4*)Wv + (size_t)v * (DM / 4) + half * 64;
        const float4* cx = sctx + half * 64;
        #pragma unroll 8
        for (int d = 0; d < 64; d += 2) {
            const float4 wa = wv[d],     ca = cx[d];
            const float4 wb = wv[d + 1], cb = cx[d + 1];
            s0a += wa.x*ca.x + wa.y*ca.y + wa.z*ca.z + wa.w*ca.w;
            s1a += wb.x*cb.x + wb.y*cb.y + wb.z*cb.z + wb.w*cb.w;
        }
        const float part = s0a + s1a;
        // pair-reduce the two halves via smem
        __syncthreads();
        ((float*)smf)[0] = 0.f;   // dummy to keep smf alive (not used below)
        float* red = (float*)(sctx + 128);   // 128 floats scratch
        if (half == 1) red[v] = part;
        __syncthreads();
        if (half == 0) out[(size_t)b * DV + v] = part + red[v];
    }
}

// ============================================================================
extern "C" void kernel_launch(void* const* d_in, const int* in_sizes, int n_in,
                              void* d_out, int out_size)
{
    const float* query = (const float*)d_in[0];   // [64, 512]
    const float* embs  = (const float*)d_in[1];   // [64, 32, 256, 512]
    const float* Wq    = (const float*)d_in[2];   // [128, 512]
    const float* Wk    = (const float*)d_in[3];   // [128, 512]
    const float* Wv    = (const float*)d_in[4];   // [128, 512]
    const float* lags  = (const float*)d_in[5];   // [256]
    const float* gates = (const float*)d_in[6];   // [256]
    const void*  ml    = (n_in > 7) ? d_in[7] : nullptr;

    prep_kernel<<<dim3(4, NB), 256>>>(query, Wq, Wk, lags, gates, ml);
    main_kernel<<<dim3(CPB, NB), 256>>>(embs, Wv, (float*)d_out);
}